// round 15
// baseline (speedup 1.0000x reference)
#include <cuda_runtime.h>
#include <cuda_bf16.h>

// Problem constants (fixed by the reference)
#define BG   128              // graphs
#define NN_  512              // nodes per graph
#define FF   128              // feature dim
#define DEG  16
#define ETOT (BG*NN_*DEG)     // 1,048,576 edges
#define NTOT (BG*NN_)         // 65,536 nodes
#define ADJ_WORDS (BG*NN_*(NN_/32))  // 4MB bitmask
#define PADN 64               // padded neighbor-list stride (multiple of 4)

// -------- device-global scratch (no allocations allowed) --------
__device__ unsigned int   g_adj[ADJ_WORDS];                  // zero-init; cleared inline each pass
__device__ unsigned int   g_nbr32[(size_t)NTOT * PADN + 4];  // byte offsets node*64 (+pad for prefetch)
__device__ float          g_dinv[NTOT];
__device__ unsigned int   g_pc[NTOT];                   // degree-sorted: node | cnt4<<16
__device__ float g_acc[(size_t)NTOT * FF];   // 32MB
__device__ float g_y[(size_t)NTOT * FF];     // 32MB
__device__ float g_pool[512 * 128];          // per-(graph-quarter) col sums
__device__ unsigned int g_wt1[16384];        // W1^T split: hi pairs / lo pairs
__device__ unsigned int g_wt2[16384];        // W2^T split

// ---------------- adjacency build ----------------
__global__ void build_adj_kernel(const int* __restrict__ ei) {
    int e = blockIdx.x * blockDim.x + threadIdx.x;
    if (e >= ETOT) return;
    int src = ei[e];
    int dst = ei[ETOT + e];
    int g  = src >> 9;         // N = 512
    int si = src & 511;
    int di = dst & 511;
    atomicOr(&g_adj[(g * 512 + si) * 16 + (di >> 5)], 1u << (di & 31));
}

// Fused: blocks [0,BG): expand bitmask -> u32 offset lists (node*64), clearing
// the bitmask inline (so no separate memset), dinv, per-graph counting sort.
// Blocks BG, BG+1: transpose + hi/lo bf16 split of W1 / W2.
__global__ void __launch_bounds__(512) expand_sort_prep_kernel(
        const float* __restrict__ W1, const float* __restrict__ W2,
        unsigned int* __restrict__ wt1, unsigned int* __restrict__ wt2) {
    int b = blockIdx.x;
    if (b >= BG) {
        const float* W = (b == BG) ? W1 : W2;
        unsigned int* wt = (b == BG) ? wt1 : wt2;
        for (int id = threadIdx.x; id < 8192; id += 512) {
            int n = id >> 6, k = (id & 63) * 2;
            float x0 = W[k * 128 + n];
            float x1 = W[(k + 1) * 128 + n];
            __nv_bfloat16 h0 = __float2bfloat16(x0);
            __nv_bfloat16 h1 = __float2bfloat16(x1);
            __nv_bfloat16 l0 = __float2bfloat16(x0 - __bfloat162float(h0));
            __nv_bfloat16 l1 = __float2bfloat16(x1 - __bfloat162float(h1));
            wt[id]        = (unsigned int)__bfloat16_as_ushort(h0) | ((unsigned int)__bfloat16_as_ushort(h1) << 16);
            wt[8192 + id] = (unsigned int)__bfloat16_as_ushort(l0) | ((unsigned int)__bfloat16_as_ushort(l1) << 16);
        }
        return;
    }

    __shared__ unsigned hist[17];
    __shared__ unsigned basep[17];
    int g = b, tid = threadIdx.x;
    int i = g * 512 + tid;

    int cnt = 0;
    unsigned* row = &g_nbr32[(size_t)i * PADN];
#pragma unroll
    for (int w = 0; w < 16; w++) {
        unsigned int bits = g_adj[i * 16 + w];
        g_adj[i * 16 + w] = 0u;          // inline clear for next pass
        while (bits) {
            int bb = __ffs(bits) - 1;
            bits &= bits - 1;
            if (cnt < PADN) row[cnt] = (unsigned)((w * 32 + bb) << 6);  // node*64
            cnt++;
        }
    }
    if (cnt > PADN) cnt = PADN;
    g_dinv[i] = (cnt > 0) ? rsqrtf((float)cnt) : 0.0f;
    int cnt4 = (cnt + 3) & ~3;
    for (int e = cnt; e < cnt4; e++) row[e] = 512u << 6;   // zero row at node 512

    if (tid < 17) hist[tid] = 0;
    __syncthreads();
    int bin = cnt4 >> 2;   // 0..16
    atomicAdd(&hist[bin], 1);
    __syncthreads();
    if (tid == 0) {
        unsigned s = 0;
        for (int k = 0; k < 17; k++) { basep[k] = s; s += hist[k]; }
    }
    __syncthreads();
    unsigned pos = atomicAdd(&basep[bin], 1);
    g_pc[g * 512 + pos] = (unsigned)tid | ((unsigned)cnt4 << 16);
}

// ---------------- packed helpers ----------------
__device__ __forceinline__ void addx2(unsigned long long& a, unsigned long long b) {
    asm("add.rn.f32x2 %0, %0, %1;" : "+l"(a) : "l"(b));
}
__device__ __forceinline__ unsigned long long mulx2(unsigned long long a, unsigned long long b) {
    unsigned long long r;
    asm("mul.rn.f32x2 %0, %1, %2;" : "=l"(r) : "l"(a), "l"(b));
    return r;
}
__device__ __forceinline__ unsigned long long packx2(float lo, float hi) {
    unsigned long long r;
    asm("mov.b64 %0, {%1, %2};" : "=l"(r) : "f"(lo), "f"(hi));
    return r;
}
__device__ __forceinline__ unsigned long long bfpair(unsigned u) {
    unsigned long long r;
    asm("{\n\t.reg .b32 lo, hi;\n\t"
        "shl.b32 lo, %1, 16;\n\t"
        "and.b32 hi, %1, 0xffff0000;\n\t"
        "mov.b64 %0, {lo, hi};\n\t}"
        : "=l"(r) : "r"(u));
    return r;
}
__device__ __forceinline__ unsigned packbf_from_x2(unsigned long long p) {
    unsigned r;
    asm("{\n\t.reg .b32 lo, hi;\n\t"
        "mov.b64 {lo, hi}, %1;\n\t"
        "cvt.rn.bf16x2.f32 %0, hi, lo;\n\t}"
        : "=r"(r) : "l"(p));
    return r;
}
__device__ __forceinline__ void unpackx2(unsigned long long p, float& lo, float& hi) {
    asm("mov.b64 {%0, %1}, %2;" : "=f"(lo), "=f"(hi) : "l"(p));
}

// ---------------- polynomial filter (unchanged from R14 best) ----------------
#define FS 32
#define UROWS 513                        // row 512 = zero row
#define UROWB 64                         // bf16 row bytes
#define POLY_U0   0
#define POLY_U1   (POLY_U0 + UROWS*UROWB)
#define POLY_DINV (POLY_U1 + UROWS*UROWB)
#define POLY_PC   (POLY_DINV + NN_*4)
#define POLY_SMEM (POLY_PC + NN_*4)

__global__ void __launch_bounds__(1024, 1) poly_kernel(const float* __restrict__ xin) {
    extern __shared__ unsigned char smraw[];
    unsigned char* ubuf0 = smraw + POLY_U0;
    unsigned char* ubuf1 = smraw + POLY_U1;
    float* dinv_s  = (float*)(smraw + POLY_DINV);
    unsigned* pc_s = (unsigned*)(smraw + POLY_PC);

    int g  = blockIdx.y;
    int fb = blockIdx.x * FS;
    int tid = threadIdx.x, w = tid >> 5, lane = tid & 31;
    int q  = lane >> 3;
    int li = lane & 7;

    const char* nbr_base = (const char*)&g_nbr32[(size_t)g * 512 * PADN];

    if (tid < 512) {
        dinv_s[tid] = g_dinv[g * 512 + tid];
        pc_s[tid]   = g_pc[g * 512 + tid];
    }
    if (tid >= 512 && tid < 528) *(unsigned*)(ubuf0 + 512 * UROWB + (tid - 512) * 4) = 0u;
    else if (tid >= 544 && tid < 560) *(unsigned*)(ubuf1 + 512 * UROWB + (tid - 544) * 4) = 0u;
    __syncthreads();

    int roff[4];
    int cntm[4];
    unsigned long long ddm[4];
    unsigned long long acc01[4], acc23[4];

    const char* xbase = (const char*)(xin + (size_t)g * 512 * FF + fb) + li * 16;
#pragma unroll
    for (int m = 0; m < 4; m++) {
        int pos = m * 128 + ((m & 1) ? (124 - 4 * w) : (4 * w)) + q;  // serpentine
        unsigned pc = pc_s[pos];
        int row = pc & 0xffffu;
        cntm[m] = pc >> 16;
        roff[m] = row << 6;
        float d = dinv_s[row];
        ddm[m] = packx2(d, d);
        float4 xv = *(const float4*)(xbase + (size_t)roff[m] * 8);
        acc01[m] = packx2(xv.x, xv.y);
        acc23[m] = packx2(xv.z, xv.w);
        uint2 uw;
        uw.x = packbf_from_x2(mulx2(ddm[m], acc01[m]));
        uw.y = packbf_from_x2(mulx2(ddm[m], acc23[m]));
        *(uint2*)(ubuf0 + roff[m] + li * 8) = uw;
    }
    __syncthreads();

    unsigned char* ucur = ubuf0;
    unsigned char* unew = ubuf1;
#pragma unroll 1
    for (int hop = 0; hop < 3; hop++) {
        const char* ucb = (const char*)ucur + li * 8;
#pragma unroll
        for (int m = 0; m < 4; m++) {
            const uint4* rowp = (const uint4*)(nbr_base + ((size_t)roff[m] << 2));
            int cnt4 = cntm[m];
            unsigned long long s01 = 0ull, s23 = 0ull;
            uint4 pk = __ldg(rowp);
#pragma unroll 1
            for (int e = 0; e < cnt4; e += 4) {
                uint4 nx = __ldg(rowp + (e >> 2) + 1);
                uint2 v0 = *(const uint2*)(ucb + pk.x);
                uint2 v1 = *(const uint2*)(ucb + pk.y);
                uint2 v2 = *(const uint2*)(ucb + pk.z);
                uint2 v3 = *(const uint2*)(ucb + pk.w);
                addx2(s01, bfpair(v0.x)); addx2(s23, bfpair(v0.y));
                addx2(s01, bfpair(v1.x)); addx2(s23, bfpair(v1.y));
                addx2(s01, bfpair(v2.x)); addx2(s23, bfpair(v2.y));
                addx2(s01, bfpair(v3.x)); addx2(s23, bfpair(v3.y));
                pk = nx;
            }
            unsigned long long z01 = mulx2(ddm[m], s01);
            unsigned long long z23 = mulx2(ddm[m], s23);
            addx2(acc01[m], z01); addx2(acc23[m], z23);
            if (hop < 2) {
                uint2 uw;
                uw.x = packbf_from_x2(mulx2(ddm[m], z01));
                uw.y = packbf_from_x2(mulx2(ddm[m], z23));
                *(uint2*)(unew + roff[m] + li * 8) = uw;
            }
        }
        __syncthreads();
        unsigned char* t = ucur; ucur = unew; unew = t;
    }

    char* ybase = (char*)(g_acc + (size_t)g * 512 * FF + fb) + li * 16;
#pragma unroll
    for (int m = 0; m < 4; m++) {
        float4 ov;
        unpackx2(acc01[m], ov.x, ov.y);
        unpackx2(acc23[m], ov.z, ov.w);
        *(float4*)(ybase + (size_t)roff[m] * 8) = ov;
    }
}

// ---------------- mma.sync GEMM + bias + relu ----------------
// 512 threads = 16 warps; warp (wr, wc) owns rows 32*wr..+31, cols 32*wc..+31
// (2 m-tiles x 4 n-tiles). 2x the warps of the previous version for latency
// hiding on the HMMA+LDS mainloop (smem layout unchanged, 1 CTA/SM).
// MODE 0: write Y. MODE 1: fused column sums of relu output -> pool.
#define ASTR 136
#define GMM_AH 0
#define GMM_AL (GMM_AH + 128*ASTR*2)
#define GMM_BH (GMM_AL + 128*ASTR*2)
#define GMM_BL (GMM_BH + 128*ASTR*2)
#define GMM_BIAS (GMM_BL + 128*ASTR*2)
#define GMM_PART (GMM_BIAS + 128*4)
#define GEMM_MMA_SMEM (GMM_PART + 4*128*4)

__device__ __forceinline__ void mma16816(float* c, const unsigned* a, const unsigned* b) {
    asm volatile(
        "mma.sync.aligned.m16n8k16.row.col.f32.bf16.bf16.f32 "
        "{%0,%1,%2,%3}, {%4,%5,%6,%7}, {%8,%9}, {%0,%1,%2,%3};"
        : "+f"(c[0]), "+f"(c[1]), "+f"(c[2]), "+f"(c[3])
        : "r"(a[0]), "r"(a[1]), "r"(a[2]), "r"(a[3]), "r"(b[0]), "r"(b[1]));
}

template <int MODE>
__global__ void __launch_bounds__(512, 1) gemm_mma_kernel(
        const float* __restrict__ A, const unsigned int* __restrict__ wt,
        const float* __restrict__ bias, float* __restrict__ Y,
        float* __restrict__ pool) {
    extern __shared__ unsigned char smg[];
    unsigned short* Ah = (unsigned short*)(smg + GMM_AH);
    unsigned short* Al = (unsigned short*)(smg + GMM_AL);
    unsigned short* Bh = (unsigned short*)(smg + GMM_BH);
    unsigned short* Bl = (unsigned short*)(smg + GMM_BL);
    float* bias_s = (float*)(smg + GMM_BIAS);
    float* part   = (float*)(smg + GMM_PART);   // [4][128]

    int tid = threadIdx.x;
    int lane = tid & 31;
    int w = tid >> 5;
    int wr = w & 3;            // row group: rows 32*wr..+31
    int wc = w >> 2;           // col group: cols 32*wc..+31  (0..3)
    size_t rowbase = (size_t)blockIdx.x * 128;

    for (int idx = tid; idx < 8192; idx += 512) {
        int n = idx >> 6, p = idx & 63;
        *(unsigned int*)&Bh[n * ASTR + 2 * p] = wt[idx];
        *(unsigned int*)&Bl[n * ASTR + 2 * p] = wt[8192 + idx];
    }
    for (int idx = tid; idx < 8192; idx += 512) {
        int r = idx >> 6, p = idx & 63;
        float2 x = *(const float2*)(A + (rowbase + r) * 128 + 2 * p);
        __nv_bfloat16 h0 = __float2bfloat16(x.x);
        __nv_bfloat16 h1 = __float2bfloat16(x.y);
        __nv_bfloat16 l0 = __float2bfloat16(x.x - __bfloat162float(h0));
        __nv_bfloat16 l1 = __float2bfloat16(x.y - __bfloat162float(h1));
        *(unsigned int*)&Ah[r * ASTR + 2 * p] =
            (unsigned int)__bfloat16_as_ushort(h0) | ((unsigned int)__bfloat16_as_ushort(h1) << 16);
        *(unsigned int*)&Al[r * ASTR + 2 * p] =
            (unsigned int)__bfloat16_as_ushort(l0) | ((unsigned int)__bfloat16_as_ushort(l1) << 16);
    }
    if (tid < 128) bias_s[tid] = bias[tid];
    __syncthreads();

    float acc[2][4][4];
#pragma unroll
    for (int mt = 0; mt < 2; mt++)
#pragma unroll
        for (int nt = 0; nt < 4; nt++)
#pragma unroll
            for (int p = 0; p < 4; p++) acc[mt][nt][p] = 0.0f;

    int frow = lane >> 2;
    int fcolb = 2 * (lane & 3);

#pragma unroll
    for (int kk = 0; kk < 8; kk++) {
        int kc = fcolb + 16 * kk;
        unsigned ah[2][4], al[2][4], bh[4][2], bl[4][2];
#pragma unroll
        for (int mt = 0; mt < 2; mt++) {
            int r0 = 32 * wr + 16 * mt + frow;
            ah[mt][0] = *(const unsigned*)&Ah[r0 * ASTR + kc];
            ah[mt][1] = *(const unsigned*)&Ah[(r0 + 8) * ASTR + kc];
            ah[mt][2] = *(const unsigned*)&Ah[r0 * ASTR + kc + 8];
            ah[mt][3] = *(const unsigned*)&Ah[(r0 + 8) * ASTR + kc + 8];
            al[mt][0] = *(const unsigned*)&Al[r0 * ASTR + kc];
            al[mt][1] = *(const unsigned*)&Al[(r0 + 8) * ASTR + kc];
            al[mt][2] = *(const unsigned*)&Al[r0 * ASTR + kc + 8];
            al[mt][3] = *(const unsigned*)&Al[(r0 + 8) * ASTR + kc + 8];
        }
#pragma unroll
        for (int nt = 0; nt < 4; nt++) {
            int n0 = 32 * wc + 8 * nt + frow;
            bh[nt][0] = *(const unsigned*)&Bh[n0 * ASTR + kc];
            bh[nt][1] = *(const unsigned*)&Bh[n0 * ASTR + kc + 8];
            bl[nt][0] = *(const unsigned*)&Bl[n0 * ASTR + kc];
            bl[nt][1] = *(const unsigned*)&Bl[n0 * ASTR + kc + 8];
        }
#pragma unroll
        for (int mt = 0; mt < 2; mt++)
#pragma unroll
            for (int nt = 0; nt < 4; nt++) {
                mma16816(acc[mt][nt], ah[mt], bh[nt]);
                mma16816(acc[mt][nt], ah[mt], bl[nt]);
                mma16816(acc[mt][nt], al[mt], bh[nt]);
            }
    }

    if (MODE == 0) {
#pragma unroll
        for (int mt = 0; mt < 2; mt++) {
            size_t r0 = rowbase + 32 * wr + 16 * mt + frow;
#pragma unroll
            for (int nt = 0; nt < 4; nt++) {
                int col = 32 * wc + 8 * nt + fcolb;
                float b0 = bias_s[col], b1 = bias_s[col + 1];
                float2 v0, v1;
                float t;
                t = acc[mt][nt][0] + b0; v0.x = t > 0 ? t : 0;
                t = acc[mt][nt][1] + b1; v0.y = t > 0 ? t : 0;
                t = acc[mt][nt][2] + b0; v1.x = t > 0 ? t : 0;
                t = acc[mt][nt][3] + b1; v1.y = t > 0 ? t : 0;
                *(float2*)(Y + r0 * 128 + col)       = v0;
                *(float2*)(Y + (r0 + 8) * 128 + col) = v1;
            }
        }
    } else {
        // column partial sums of relu output over this warp's 32 rows
        float cs[4][2];
#pragma unroll
        for (int nt = 0; nt < 4; nt++) {
            int col = 32 * wc + 8 * nt + fcolb;
            float b0 = bias_s[col], b1 = bias_s[col + 1];
            float a0 = 0.f, a1 = 0.f;
#pragma unroll
            for (int mt = 0; mt < 2; mt++) {
                float t;
                t = acc[mt][nt][0] + b0; a0 += (t > 0 ? t : 0);
                t = acc[mt][nt][2] + b0; a0 += (t > 0 ? t : 0);
                t = acc[mt][nt][1] + b1; a1 += (t > 0 ? t : 0);
                t = acc[mt][nt][3] + b1; a1 += (t > 0 ? t : 0);
            }
            cs[nt][0] = a0; cs[nt][1] = a1;
        }
#pragma unroll
        for (int nt = 0; nt < 4; nt++) {
#pragma unroll
            for (int sft = 4; sft < 32; sft <<= 1) {
                cs[nt][0] += __shfl_xor_sync(0xffffffffu, cs[nt][0], sft);
                cs[nt][1] += __shfl_xor_sync(0xffffffffu, cs[nt][1], sft);
            }
        }
        if (lane < 4) {
#pragma unroll
            for (int nt = 0; nt < 4; nt++) {
                part[wr * 128 + 32 * wc + 8 * nt + 2 * lane]     = cs[nt][0];
                part[wr * 128 + 32 * wc + 8 * nt + 2 * lane + 1] = cs[nt][1];
            }
        }
        __syncthreads();
        if (tid < 128) {
            pool[(size_t)blockIdx.x * 128 + tid] =
                part[tid] + part[128 + tid] + part[256 + tid] + part[384 + tid];
        }
    }
}

// ---------------- head: mean pool (from partials) -> MLP ----------------
__global__ void __launch_bounds__(128) head_kernel(
        const float* __restrict__ pool,
        const float* __restrict__ Wr1, const float* __restrict__ br1,
        const float* __restrict__ Wr2, const float* __restrict__ br2,
        float* __restrict__ out) {
    __shared__ float hs[128];
    __shared__ float rs[64];
    int g = blockIdx.x;
    int tid = threadIdx.x;

    {
        const float* p = pool + (size_t)(4 * g) * 128 + tid;
        hs[tid] = (p[0] + p[128] + p[256] + p[384]) * (1.0f / 512.0f);
    }
    __syncthreads();

    if (tid < 64) {
        float a = br1[tid];
        for (int k = 0; k < 128; k++) a += hs[k] * Wr1[k * 64 + tid];
        rs[tid] = a > 0 ? a : 0;
    }
    __syncthreads();

    if (tid == 0) {
        float a = br2[0];
        for (int o = 0; o < 64; o++) a += rs[o] * Wr2[o];
        out[g] = a;
    }
}

// ---------------- launch ----------------
extern "C" void kernel_launch(void* const* d_in, const int* in_sizes, int n_in,
                              void* d_out, int out_size) {
    const float* X   = (const float*)d_in[0];
    const int*   ei  = (const int*)d_in[2];
    const float* W1  = (const float*)d_in[3];
    const float* b1  = (const float*)d_in[4];
    const float* W2  = (const float*)d_in[5];
    const float* b2  = (const float*)d_in[6];
    const float* Wr1 = (const float*)d_in[7];
    const float* br1 = (const float*)d_in[8];
    const float* Wr2 = (const float*)d_in[9];
    const float* br2 = (const float*)d_in[10];
    float* out = (float*)d_out;

    cudaFuncSetAttribute(poly_kernel, cudaFuncAttributeMaxDynamicSharedMemorySize, POLY_SMEM);
    cudaFuncSetAttribute(gemm_mma_kernel<0>, cudaFuncAttributeMaxDynamicSharedMemorySize, GEMM_MMA_SMEM);
    cudaFuncSetAttribute(gemm_mma_kernel<1>, cudaFuncAttributeMaxDynamicSharedMemorySize, GEMM_MMA_SMEM);

    void* yaddr = nullptr;  cudaGetSymbolAddress(&yaddr, g_y);
    float* Yp = (float*)yaddr;
    void* aaddr = nullptr;  cudaGetSymbolAddress(&aaddr, g_acc);
    const float* Ap = (const float*)aaddr;
    void* w1addr = nullptr; cudaGetSymbolAddress(&w1addr, g_wt1);
    void* w2addr = nullptr; cudaGetSymbolAddress(&w2addr, g_wt2);
    void* pooladdr = nullptr; cudaGetSymbolAddress(&pooladdr, g_pool);
    float* Pp = (float*)pooladdr;

    // adjacency (rebuilt every call; g_adj cleared inline by expand each pass,
    // zero-initialized on first use)
    build_adj_kernel<<<ETOT / 256, 256>>>(ei);
    expand_sort_prep_kernel<<<BG + 2, 512>>>(W1, W2, (unsigned int*)w1addr, (unsigned int*)w2addr);

    dim3 pgrid(FF / FS, BG);

    // layer 1
    poly_kernel<<<pgrid, 1024, POLY_SMEM>>>(X);
    gemm_mma_kernel<0><<<NTOT / 128, 512, GEMM_MMA_SMEM>>>(Ap, (const unsigned int*)w1addr, b1, Yp, nullptr);
    // layer 2 (GEMM fuses the mean-pool partial sums; no Y write)
    poly_kernel<<<pgrid, 1024, POLY_SMEM>>>(Yp);
    gemm_mma_kernel<1><<<NTOT / 128, 512, GEMM_MMA_SMEM>>>(Ap, (const unsigned int*)w2addr, b2, nullptr, Pp);
    // head
    head_kernel<<<BG, 128>>>(Pp, Wr1, br1, Wr2, br2, out);
}

// round 16
// speedup vs baseline: 1.0778x; 1.0778x over previous
#include <cuda_runtime.h>
#include <cuda_bf16.h>

// Problem constants (fixed by the reference)
#define BG   128              // graphs
#define NN_  512              // nodes per graph
#define FF   128              // feature dim
#define DEG  16
#define ETOT (BG*NN_*DEG)     // 1,048,576 edges
#define NTOT (BG*NN_)         // 65,536 nodes
#define ADJ_WORDS (BG*NN_*(NN_/32))  // 4MB bitmask
#define PADN 64               // padded neighbor-list stride (multiple of 4)

// -------- device-global scratch (no allocations allowed) --------
__device__ unsigned int   g_adj[ADJ_WORDS];                  // zero-init; cleared inline each pass
__device__ unsigned int   g_nbr32[(size_t)NTOT * PADN + 4];  // byte offsets node*64 (+pad for prefetch)
__device__ float          g_dinv[NTOT];
__device__ unsigned int   g_pc[NTOT];                   // degree-sorted: node | cnt4<<16
__device__ float g_acc[(size_t)NTOT * FF];   // 32MB
__device__ float g_y[(size_t)NTOT * FF];     // 32MB
__device__ float g_pool[512 * 128];          // per-(graph-quarter) col sums
__device__ unsigned int g_wt1[16384];        // W1^T split: hi pairs / lo pairs
__device__ unsigned int g_wt2[16384];        // W2^T split

// ---------------- adjacency build ----------------
__global__ void build_adj_kernel(const int* __restrict__ ei) {
    int e = blockIdx.x * blockDim.x + threadIdx.x;
    if (e >= ETOT) return;
    int src = ei[e];
    int dst = ei[ETOT + e];
    int g  = src >> 9;         // N = 512
    int si = src & 511;
    int di = dst & 511;
    atomicOr(&g_adj[(g * 512 + si) * 16 + (di >> 5)], 1u << (di & 31));
}

// Fused: blocks [0,BG): expand bitmask -> u32 offset lists (node*64), clearing
// the bitmask inline (no separate memset), dinv, per-graph counting sort.
// Blocks BG, BG+1: transpose + hi/lo bf16 split of W1 / W2.
__global__ void __launch_bounds__(512) expand_sort_prep_kernel(
        const float* __restrict__ W1, const float* __restrict__ W2,
        unsigned int* __restrict__ wt1, unsigned int* __restrict__ wt2) {
    int b = blockIdx.x;
    if (b >= BG) {
        const float* W = (b == BG) ? W1 : W2;
        unsigned int* wt = (b == BG) ? wt1 : wt2;
        for (int id = threadIdx.x; id < 8192; id += 512) {
            int n = id >> 6, k = (id & 63) * 2;
            float x0 = W[k * 128 + n];
            float x1 = W[(k + 1) * 128 + n];
            __nv_bfloat16 h0 = __float2bfloat16(x0);
            __nv_bfloat16 h1 = __float2bfloat16(x1);
            __nv_bfloat16 l0 = __float2bfloat16(x0 - __bfloat162float(h0));
            __nv_bfloat16 l1 = __float2bfloat16(x1 - __bfloat162float(h1));
            wt[id]        = (unsigned int)__bfloat16_as_ushort(h0) | ((unsigned int)__bfloat16_as_ushort(h1) << 16);
            wt[8192 + id] = (unsigned int)__bfloat16_as_ushort(l0) | ((unsigned int)__bfloat16_as_ushort(l1) << 16);
        }
        return;
    }

    __shared__ unsigned hist[17];
    __shared__ unsigned basep[17];
    int g = b, tid = threadIdx.x;
    int i = g * 512 + tid;

    int cnt = 0;
    unsigned* row = &g_nbr32[(size_t)i * PADN];
#pragma unroll
    for (int w = 0; w < 16; w++) {
        unsigned int bits = g_adj[i * 16 + w];
        g_adj[i * 16 + w] = 0u;          // inline clear for next pass
        while (bits) {
            int bb = __ffs(bits) - 1;
            bits &= bits - 1;
            if (cnt < PADN) row[cnt] = (unsigned)((w * 32 + bb) << 6);  // node*64
            cnt++;
        }
    }
    if (cnt > PADN) cnt = PADN;
    g_dinv[i] = (cnt > 0) ? rsqrtf((float)cnt) : 0.0f;
    int cnt4 = (cnt + 3) & ~3;
    for (int e = cnt; e < cnt4; e++) row[e] = 512u << 6;   // zero row at node 512

    if (tid < 17) hist[tid] = 0;
    __syncthreads();
    int bin = cnt4 >> 2;   // 0..16
    atomicAdd(&hist[bin], 1);
    __syncthreads();
    if (tid == 0) {
        unsigned s = 0;
        for (int k = 0; k < 17; k++) { basep[k] = s; s += hist[k]; }
    }
    __syncthreads();
    unsigned pos = atomicAdd(&basep[bin], 1);
    g_pc[g * 512 + pos] = (unsigned)tid | ((unsigned)cnt4 << 16);
}

// ---------------- packed helpers ----------------
__device__ __forceinline__ void addx2(unsigned long long& a, unsigned long long b) {
    asm("add.rn.f32x2 %0, %0, %1;" : "+l"(a) : "l"(b));
}
__device__ __forceinline__ unsigned long long mulx2(unsigned long long a, unsigned long long b) {
    unsigned long long r;
    asm("mul.rn.f32x2 %0, %1, %2;" : "=l"(r) : "l"(a), "l"(b));
    return r;
}
__device__ __forceinline__ unsigned long long packx2(float lo, float hi) {
    unsigned long long r;
    asm("mov.b64 %0, {%1, %2};" : "=l"(r) : "f"(lo), "f"(hi));
    return r;
}
__device__ __forceinline__ unsigned long long bfpair(unsigned u) {
    unsigned long long r;
    asm("{\n\t.reg .b32 lo, hi;\n\t"
        "shl.b32 lo, %1, 16;\n\t"
        "and.b32 hi, %1, 0xffff0000;\n\t"
        "mov.b64 %0, {lo, hi};\n\t}"
        : "=l"(r) : "r"(u));
    return r;
}
__device__ __forceinline__ unsigned packbf_from_x2(unsigned long long p) {
    unsigned r;
    asm("{\n\t.reg .b32 lo, hi;\n\t"
        "mov.b64 {lo, hi}, %1;\n\t"
        "cvt.rn.bf16x2.f32 %0, hi, lo;\n\t}"
        : "=r"(r) : "l"(p));
    return r;
}
__device__ __forceinline__ void unpackx2(unsigned long long p, float& lo, float& hi) {
    asm("mov.b64 {%0, %1}, %2;" : "=f"(lo), "=f"(hi) : "l"(p));
}

// ---------------- polynomial filter (R14 best; unchanged) ----------------
#define FS 32
#define UROWS 513                        // row 512 = zero row
#define UROWB 64                         // bf16 row bytes
#define POLY_U0   0
#define POLY_U1   (POLY_U0 + UROWS*UROWB)
#define POLY_DINV (POLY_U1 + UROWS*UROWB)
#define POLY_PC   (POLY_DINV + NN_*4)
#define POLY_SMEM (POLY_PC + NN_*4)

__global__ void __launch_bounds__(1024, 1) poly_kernel(const float* __restrict__ xin) {
    extern __shared__ unsigned char smraw[];
    unsigned char* ubuf0 = smraw + POLY_U0;
    unsigned char* ubuf1 = smraw + POLY_U1;
    float* dinv_s  = (float*)(smraw + POLY_DINV);
    unsigned* pc_s = (unsigned*)(smraw + POLY_PC);

    int g  = blockIdx.y;
    int fb = blockIdx.x * FS;
    int tid = threadIdx.x, w = tid >> 5, lane = tid & 31;
    int q  = lane >> 3;
    int li = lane & 7;

    const char* nbr_base = (const char*)&g_nbr32[(size_t)g * 512 * PADN];

    if (tid < 512) {
        dinv_s[tid] = g_dinv[g * 512 + tid];
        pc_s[tid]   = g_pc[g * 512 + tid];
    }
    if (tid >= 512 && tid < 528) *(unsigned*)(ubuf0 + 512 * UROWB + (tid - 512) * 4) = 0u;
    else if (tid >= 544 && tid < 560) *(unsigned*)(ubuf1 + 512 * UROWB + (tid - 544) * 4) = 0u;
    __syncthreads();

    int roff[4];
    int cntm[4];
    unsigned long long ddm[4];
    unsigned long long acc01[4], acc23[4];

    const char* xbase = (const char*)(xin + (size_t)g * 512 * FF + fb) + li * 16;
#pragma unroll
    for (int m = 0; m < 4; m++) {
        int pos = m * 128 + ((m & 1) ? (124 - 4 * w) : (4 * w)) + q;  // serpentine
        unsigned pc = pc_s[pos];
        int row = pc & 0xffffu;
        cntm[m] = pc >> 16;
        roff[m] = row << 6;
        float d = dinv_s[row];
        ddm[m] = packx2(d, d);
        float4 xv = *(const float4*)(xbase + (size_t)roff[m] * 8);
        acc01[m] = packx2(xv.x, xv.y);
        acc23[m] = packx2(xv.z, xv.w);
        uint2 uw;
        uw.x = packbf_from_x2(mulx2(ddm[m], acc01[m]));
        uw.y = packbf_from_x2(mulx2(ddm[m], acc23[m]));
        *(uint2*)(ubuf0 + roff[m] + li * 8) = uw;
    }
    __syncthreads();

    unsigned char* ucur = ubuf0;
    unsigned char* unew = ubuf1;
#pragma unroll 1
    for (int hop = 0; hop < 3; hop++) {
        const char* ucb = (const char*)ucur + li * 8;
#pragma unroll
        for (int m = 0; m < 4; m++) {
            const uint4* rowp = (const uint4*)(nbr_base + ((size_t)roff[m] << 2));
            int cnt4 = cntm[m];
            unsigned long long s01 = 0ull, s23 = 0ull;
            uint4 pk = __ldg(rowp);
#pragma unroll 1
            for (int e = 0; e < cnt4; e += 4) {
                uint4 nx = __ldg(rowp + (e >> 2) + 1);
                uint2 v0 = *(const uint2*)(ucb + pk.x);
                uint2 v1 = *(const uint2*)(ucb + pk.y);
                uint2 v2 = *(const uint2*)(ucb + pk.z);
                uint2 v3 = *(const uint2*)(ucb + pk.w);
                addx2(s01, bfpair(v0.x)); addx2(s23, bfpair(v0.y));
                addx2(s01, bfpair(v1.x)); addx2(s23, bfpair(v1.y));
                addx2(s01, bfpair(v2.x)); addx2(s23, bfpair(v2.y));
                addx2(s01, bfpair(v3.x)); addx2(s23, bfpair(v3.y));
                pk = nx;
            }
            unsigned long long z01 = mulx2(ddm[m], s01);
            unsigned long long z23 = mulx2(ddm[m], s23);
            addx2(acc01[m], z01); addx2(acc23[m], z23);
            if (hop < 2) {
                uint2 uw;
                uw.x = packbf_from_x2(mulx2(ddm[m], z01));
                uw.y = packbf_from_x2(mulx2(ddm[m], z23));
                *(uint2*)(unew + roff[m] + li * 8) = uw;
            }
        }
        __syncthreads();
        unsigned char* t = ucur; ucur = unew; unew = t;
    }

    char* ybase = (char*)(g_acc + (size_t)g * 512 * FF + fb) + li * 16;
#pragma unroll
    for (int m = 0; m < 4; m++) {
        float4 ov;
        unpackx2(acc01[m], ov.x, ov.y);
        unpackx2(acc23[m], ov.z, ov.w);
        *(float4*)(ybase + (size_t)roff[m] * 8) = ov;
    }
}

// ---------------- mma.sync GEMM + bias + relu (R14 best: 256 thr, 32x64 tiles) ----
// MODE 0: write Y. MODE 1: fused column sums of relu output -> pool.
#define ASTR 136
#define GMM_AH 0
#define GMM_AL (GMM_AH + 128*ASTR*2)
#define GMM_BH (GMM_AL + 128*ASTR*2)
#define GMM_BL (GMM_BH + 128*ASTR*2)
#define GMM_BIAS (GMM_BL + 128*ASTR*2)
#define GMM_PART (GMM_BIAS + 128*4)
#define GEMM_MMA_SMEM (GMM_PART + 4*128*4)

__device__ __forceinline__ void mma16816(float* c, const unsigned* a, const unsigned* b) {
    asm volatile(
        "mma.sync.aligned.m16n8k16.row.col.f32.bf16.bf16.f32 "
        "{%0,%1,%2,%3}, {%4,%5,%6,%7}, {%8,%9}, {%0,%1,%2,%3};"
        : "+f"(c[0]), "+f"(c[1]), "+f"(c[2]), "+f"(c[3])
        : "r"(a[0]), "r"(a[1]), "r"(a[2]), "r"(a[3]), "r"(b[0]), "r"(b[1]));
}

template <int MODE>
__global__ void __launch_bounds__(256, 1) gemm_mma_kernel(
        const float* __restrict__ A, const unsigned int* __restrict__ wt,
        const float* __restrict__ bias, float* __restrict__ Y,
        float* __restrict__ pool) {
    extern __shared__ unsigned char smg[];
    unsigned short* Ah = (unsigned short*)(smg + GMM_AH);
    unsigned short* Al = (unsigned short*)(smg + GMM_AL);
    unsigned short* Bh = (unsigned short*)(smg + GMM_BH);
    unsigned short* Bl = (unsigned short*)(smg + GMM_BL);
    float* bias_s = (float*)(smg + GMM_BIAS);
    float* part   = (float*)(smg + GMM_PART);   // [4][128]

    int tid = threadIdx.x;
    int lane = tid & 31;
    int w = tid >> 5;
    int wr = w & 3;
    int wc = w >> 2;
    size_t rowbase = (size_t)blockIdx.x * 128;

    for (int idx = tid; idx < 8192; idx += 256) {
        int n = idx >> 6, p = idx & 63;
        *(unsigned int*)&Bh[n * ASTR + 2 * p] = wt[idx];
        *(unsigned int*)&Bl[n * ASTR + 2 * p] = wt[8192 + idx];
    }
    for (int idx = tid; idx < 8192; idx += 256) {
        int r = idx >> 6, p = idx & 63;
        float2 x = *(const float2*)(A + (rowbase + r) * 128 + 2 * p);
        __nv_bfloat16 h0 = __float2bfloat16(x.x);
        __nv_bfloat16 h1 = __float2bfloat16(x.y);
        __nv_bfloat16 l0 = __float2bfloat16(x.x - __bfloat162float(h0));
        __nv_bfloat16 l1 = __float2bfloat16(x.y - __bfloat162float(h1));
        *(unsigned int*)&Ah[r * ASTR + 2 * p] =
            (unsigned int)__bfloat16_as_ushort(h0) | ((unsigned int)__bfloat16_as_ushort(h1) << 16);
        *(unsigned int*)&Al[r * ASTR + 2 * p] =
            (unsigned int)__bfloat16_as_ushort(l0) | ((unsigned int)__bfloat16_as_ushort(l1) << 16);
    }
    if (tid < 128) bias_s[tid] = bias[tid];
    __syncthreads();

    float acc[2][8][4];
#pragma unroll
    for (int mt = 0; mt < 2; mt++)
#pragma unroll
        for (int nt = 0; nt < 8; nt++)
#pragma unroll
            for (int p = 0; p < 4; p++) acc[mt][nt][p] = 0.0f;

    int frow = lane >> 2;
    int fcolb = 2 * (lane & 3);

#pragma unroll
    for (int kk = 0; kk < 8; kk++) {
        int kc = fcolb + 16 * kk;
        unsigned ah[2][4], al[2][4], bh[8][2], bl[8][2];
#pragma unroll
        for (int mt = 0; mt < 2; mt++) {
            int r0 = 32 * wr + 16 * mt + frow;
            ah[mt][0] = *(const unsigned*)&Ah[r0 * ASTR + kc];
            ah[mt][1] = *(const unsigned*)&Ah[(r0 + 8) * ASTR + kc];
            ah[mt][2] = *(const unsigned*)&Ah[r0 * ASTR + kc + 8];
            ah[mt][3] = *(const unsigned*)&Ah[(r0 + 8) * ASTR + kc + 8];
            al[mt][0] = *(const unsigned*)&Al[r0 * ASTR + kc];
            al[mt][1] = *(const unsigned*)&Al[(r0 + 8) * ASTR + kc];
            al[mt][2] = *(const unsigned*)&Al[r0 * ASTR + kc + 8];
            al[mt][3] = *(const unsigned*)&Al[(r0 + 8) * ASTR + kc + 8];
        }
#pragma unroll
        for (int nt = 0; nt < 8; nt++) {
            int n0 = 64 * wc + 8 * nt + frow;
            bh[nt][0] = *(const unsigned*)&Bh[n0 * ASTR + kc];
            bh[nt][1] = *(const unsigned*)&Bh[n0 * ASTR + kc + 8];
            bl[nt][0] = *(const unsigned*)&Bl[n0 * ASTR + kc];
            bl[nt][1] = *(const unsigned*)&Bl[n0 * ASTR + kc + 8];
        }
#pragma unroll
        for (int mt = 0; mt < 2; mt++)
#pragma unroll
            for (int nt = 0; nt < 8; nt++) {
                mma16816(acc[mt][nt], ah[mt], bh[nt]);
                mma16816(acc[mt][nt], ah[mt], bl[nt]);
                mma16816(acc[mt][nt], al[mt], bh[nt]);
            }
    }

    if (MODE == 0) {
#pragma unroll
        for (int mt = 0; mt < 2; mt++) {
            size_t r0 = rowbase + 32 * wr + 16 * mt + frow;
#pragma unroll
            for (int nt = 0; nt < 8; nt++) {
                int col = 64 * wc + 8 * nt + fcolb;
                float b0 = bias_s[col], b1 = bias_s[col + 1];
                float2 v0, v1;
                float t;
                t = acc[mt][nt][0] + b0; v0.x = t > 0 ? t : 0;
                t = acc[mt][nt][1] + b1; v0.y = t > 0 ? t : 0;
                t = acc[mt][nt][2] + b0; v1.x = t > 0 ? t : 0;
                t = acc[mt][nt][3] + b1; v1.y = t > 0 ? t : 0;
                *(float2*)(Y + r0 * 128 + col)       = v0;
                *(float2*)(Y + (r0 + 8) * 128 + col) = v1;
            }
        }
    } else {
        // column partial sums of relu output over this CTA's 128 rows
        float cs[8][2];
#pragma unroll
        for (int nt = 0; nt < 8; nt++) {
            int col = 64 * wc + 8 * nt + fcolb;
            float b0 = bias_s[col], b1 = bias_s[col + 1];
            float a0 = 0.f, a1 = 0.f;
#pragma unroll
            for (int mt = 0; mt < 2; mt++) {
                float t;
                t = acc[mt][nt][0] + b0; a0 += (t > 0 ? t : 0);
                t = acc[mt][nt][2] + b0; a0 += (t > 0 ? t : 0);
                t = acc[mt][nt][1] + b1; a1 += (t > 0 ? t : 0);
                t = acc[mt][nt][3] + b1; a1 += (t > 0 ? t : 0);
            }
            cs[nt][0] = a0; cs[nt][1] = a1;
        }
#pragma unroll
        for (int nt = 0; nt < 8; nt++) {
#pragma unroll
            for (int sft = 4; sft < 32; sft <<= 1) {
                cs[nt][0] += __shfl_xor_sync(0xffffffffu, cs[nt][0], sft);
                cs[nt][1] += __shfl_xor_sync(0xffffffffu, cs[nt][1], sft);
            }
        }
        if (lane < 4) {
#pragma unroll
            for (int nt = 0; nt < 8; nt++) {
                part[wr * 128 + 64 * wc + 8 * nt + 2 * lane]     = cs[nt][0];
                part[wr * 128 + 64 * wc + 8 * nt + 2 * lane + 1] = cs[nt][1];
            }
        }
        __syncthreads();
        if (tid < 128) {
            pool[(size_t)blockIdx.x * 128 + tid] =
                part[tid] + part[128 + tid] + part[256 + tid] + part[384 + tid];
        }
    }
}

// ---------------- head: mean pool (from partials) -> MLP ----------------
__global__ void __launch_bounds__(128) head_kernel(
        const float* __restrict__ pool,
        const float* __restrict__ Wr1, const float* __restrict__ br1,
        const float* __restrict__ Wr2, const float* __restrict__ br2,
        float* __restrict__ out) {
    __shared__ float hs[128];
    __shared__ float rs[64];
    int g = blockIdx.x;
    int tid = threadIdx.x;

    {
        const float* p = pool + (size_t)(4 * g) * 128 + tid;
        hs[tid] = (p[0] + p[128] + p[256] + p[384]) * (1.0f / 512.0f);
    }
    __syncthreads();

    if (tid < 64) {
        float a = br1[tid];
        for (int k = 0; k < 128; k++) a += hs[k] * Wr1[k * 64 + tid];
        rs[tid] = a > 0 ? a : 0;
    }
    __syncthreads();

    if (tid == 0) {
        float a = br2[0];
        for (int o = 0; o < 64; o++) a += rs[o] * Wr2[o];
        out[g] = a;
    }
}

// ---------------- launch ----------------
extern "C" void kernel_launch(void* const* d_in, const int* in_sizes, int n_in,
                              void* d_out, int out_size) {
    const float* X   = (const float*)d_in[0];
    const int*   ei  = (const int*)d_in[2];
    const float* W1  = (const float*)d_in[3];
    const float* b1  = (const float*)d_in[4];
    const float* W2  = (const float*)d_in[5];
    const float* b2  = (const float*)d_in[6];
    const float* Wr1 = (const float*)d_in[7];
    const float* br1 = (const float*)d_in[8];
    const float* Wr2 = (const float*)d_in[9];
    const float* br2 = (const float*)d_in[10];
    float* out = (float*)d_out;

    cudaFuncSetAttribute(poly_kernel, cudaFuncAttributeMaxDynamicSharedMemorySize, POLY_SMEM);
    cudaFuncSetAttribute(gemm_mma_kernel<0>, cudaFuncAttributeMaxDynamicSharedMemorySize, GEMM_MMA_SMEM);
    cudaFuncSetAttribute(gemm_mma_kernel<1>, cudaFuncAttributeMaxDynamicSharedMemorySize, GEMM_MMA_SMEM);

    void* yaddr = nullptr;  cudaGetSymbolAddress(&yaddr, g_y);
    float* Yp = (float*)yaddr;
    void* aaddr = nullptr;  cudaGetSymbolAddress(&aaddr, g_acc);
    const float* Ap = (const float*)aaddr;
    void* w1addr = nullptr; cudaGetSymbolAddress(&w1addr, g_wt1);
    void* w2addr = nullptr; cudaGetSymbolAddress(&w2addr, g_wt2);
    void* pooladdr = nullptr; cudaGetSymbolAddress(&pooladdr, g_pool);
    float* Pp = (float*)pooladdr;

    // adjacency (rebuilt every call; g_adj cleared inline by expand each pass,
    // zero-initialized on first use)
    build_adj_kernel<<<ETOT / 256, 256>>>(ei);
    expand_sort_prep_kernel<<<BG + 2, 512>>>(W1, W2, (unsigned int*)w1addr, (unsigned int*)w2addr);

    dim3 pgrid(FF / FS, BG);

    // layer 1
    poly_kernel<<<pgrid, 1024, POLY_SMEM>>>(X);
    gemm_mma_kernel<0><<<NTOT / 128, 256, GEMM_MMA_SMEM>>>(Ap, (const unsigned int*)w1addr, b1, Yp, nullptr);
    // layer 2 (GEMM fuses the mean-pool partial sums; no Y write)
    poly_kernel<<<pgrid, 1024, POLY_SMEM>>>(Yp);
    gemm_mma_kernel<1><<<NTOT / 128, 256, GEMM_MMA_SMEM>>>(Ap, (const unsigned int*)w2addr, b2, nullptr, Pp);
    // head
    head_kernel<<<BG, 128>>>(Pp, Wr1, br1, Wr2, br2, out);
}

// round 17
// speedup vs baseline: 1.1781x; 1.0930x over previous
#include <cuda_runtime.h>
#include <cuda_bf16.h>

// Problem constants (fixed by the reference)
#define BG   128              // graphs
#define NN_  512              // nodes per graph
#define FF   128              // feature dim
#define DEG  16
#define ETOT (BG*NN_*DEG)     // 1,048,576 edges
#define NTOT (BG*NN_)         // 65,536 nodes
#define ADJ_WORDS (BG*NN_*(NN_/32))  // 4MB bitmask
#define PADN 64               // padded neighbor-list stride (multiple of 4)

// -------- device-global scratch (no allocations allowed) --------
__device__ unsigned int   g_adj[ADJ_WORDS];
__device__ unsigned int   g_nbr32[(size_t)NTOT * PADN + 4];  // byte offsets node*64 (+pad for prefetch)
__device__ float          g_dinv[NTOT];
__device__ unsigned int   g_pc[NTOT];                   // degree-sorted: node | cnt4<<16
__device__ float g_acc[(size_t)NTOT * FF];   // 32MB
__device__ float g_y[(size_t)NTOT * FF];     // 32MB
__device__ float g_pool[512 * 128];          // per-(graph-quarter) col sums
__device__ unsigned int g_wt1[16384];        // W1^T split: hi pairs / lo pairs
__device__ unsigned int g_wt2[16384];        // W2^T split

// ---------------- adjacency build ----------------
__global__ void build_adj_kernel(const int* __restrict__ ei) {
    int e = blockIdx.x * blockDim.x + threadIdx.x;
    if (e >= ETOT) return;
    int src = ei[e];
    int dst = ei[ETOT + e];
    int g  = src >> 9;         // N = 512
    int si = src & 511;
    int di = dst & 511;
    atomicOr(&g_adj[(g * 512 + si) * 16 + (di >> 5)], 1u << (di & 31));
}

// Expand bitmask -> u32 byte-offset lists (node*64), dinv, per-graph counting
// sort by degree -> g_pc. One block per graph. (R14 layout: separate memset.)
__global__ void __launch_bounds__(512) expand_sort_kernel() {
    __shared__ unsigned hist[17];
    __shared__ unsigned basep[17];
    int g = blockIdx.x, tid = threadIdx.x;
    int i = g * 512 + tid;

    int cnt = 0;
    unsigned* row = &g_nbr32[(size_t)i * PADN];
#pragma unroll
    for (int w = 0; w < 16; w++) {
        unsigned int bits = g_adj[i * 16 + w];
        while (bits) {
            int b = __ffs(bits) - 1;
            bits &= bits - 1;
            if (cnt < PADN) row[cnt] = (unsigned)((w * 32 + b) << 6);  // node*64
            cnt++;
        }
    }
    if (cnt > PADN) cnt = PADN;
    g_dinv[i] = (cnt > 0) ? rsqrtf((float)cnt) : 0.0f;
    int cnt4 = (cnt + 3) & ~3;
    for (int e = cnt; e < cnt4; e++) row[e] = 512u << 6;   // zero row at node 512

    if (tid < 17) hist[tid] = 0;
    __syncthreads();
    int bin = cnt4 >> 2;   // 0..16
    atomicAdd(&hist[bin], 1);
    __syncthreads();
    if (tid == 0) {
        unsigned s = 0;
        for (int k = 0; k < 17; k++) { basep[k] = s; s += hist[k]; }
    }
    __syncthreads();
    unsigned pos = atomicAdd(&basep[bin], 1);
    g_pc[g * 512 + pos] = (unsigned)tid | ((unsigned)cnt4 << 16);
}

// Transpose + hi/lo bf16 split of both weights in one launch.
__global__ void prep_w_kernel(const float* __restrict__ W1, const float* __restrict__ W2,
                              unsigned int* __restrict__ wt1, unsigned int* __restrict__ wt2) {
    int idx = blockIdx.x * blockDim.x + threadIdx.x;
    const float* W = (idx < 8192) ? W1 : W2;
    unsigned int* wt = (idx < 8192) ? wt1 : wt2;
    int id = idx & 8191;
    int n = id >> 6, k = (id & 63) * 2;
    float x0 = W[k * 128 + n];
    float x1 = W[(k + 1) * 128 + n];
    __nv_bfloat16 h0 = __float2bfloat16(x0);
    __nv_bfloat16 h1 = __float2bfloat16(x1);
    __nv_bfloat16 l0 = __float2bfloat16(x0 - __bfloat162float(h0));
    __nv_bfloat16 l1 = __float2bfloat16(x1 - __bfloat162float(h1));
    wt[id]        = (unsigned int)__bfloat16_as_ushort(h0) | ((unsigned int)__bfloat16_as_ushort(h1) << 16);
    wt[8192 + id] = (unsigned int)__bfloat16_as_ushort(l0) | ((unsigned int)__bfloat16_as_ushort(l1) << 16);
}

// ---------------- packed helpers ----------------
__device__ __forceinline__ void addx2(unsigned long long& a, unsigned long long b) {
    asm("add.rn.f32x2 %0, %0, %1;" : "+l"(a) : "l"(b));
}
__device__ __forceinline__ unsigned long long mulx2(unsigned long long a, unsigned long long b) {
    unsigned long long r;
    asm("mul.rn.f32x2 %0, %1, %2;" : "=l"(r) : "l"(a), "l"(b));
    return r;
}
__device__ __forceinline__ unsigned long long packx2(float lo, float hi) {
    unsigned long long r;
    asm("mov.b64 %0, {%1, %2};" : "=l"(r) : "f"(lo), "f"(hi));
    return r;
}
__device__ __forceinline__ unsigned long long bfpair(unsigned u) {
    unsigned long long r;
    asm("{\n\t.reg .b32 lo, hi;\n\t"
        "shl.b32 lo, %1, 16;\n\t"
        "and.b32 hi, %1, 0xffff0000;\n\t"
        "mov.b64 %0, {lo, hi};\n\t}"
        : "=l"(r) : "r"(u));
    return r;
}
__device__ __forceinline__ unsigned packbf_from_x2(unsigned long long p) {
    unsigned r;
    asm("{\n\t.reg .b32 lo, hi;\n\t"
        "mov.b64 {lo, hi}, %1;\n\t"
        "cvt.rn.bf16x2.f32 %0, hi, lo;\n\t}"
        : "=r"(r) : "l"(p));
    return r;
}
__device__ __forceinline__ void unpackx2(unsigned long long p, float& lo, float& hi) {
    asm("mov.b64 {%0, %1}, %2;" : "=f"(lo), "=f"(hi) : "l"(p));
}

// ---------------- polynomial filter (R14 best; unchanged) ----------------
#define FS 32
#define UROWS 513                        // row 512 = zero row
#define UROWB 64                         // bf16 row bytes
#define POLY_U0   0
#define POLY_U1   (POLY_U0 + UROWS*UROWB)
#define POLY_DINV (POLY_U1 + UROWS*UROWB)
#define POLY_PC   (POLY_DINV + NN_*4)
#define POLY_SMEM (POLY_PC + NN_*4)

__global__ void __launch_bounds__(1024, 1) poly_kernel(const float* __restrict__ xin) {
    extern __shared__ unsigned char smraw[];
    unsigned char* ubuf0 = smraw + POLY_U0;
    unsigned char* ubuf1 = smraw + POLY_U1;
    float* dinv_s  = (float*)(smraw + POLY_DINV);
    unsigned* pc_s = (unsigned*)(smraw + POLY_PC);

    int g  = blockIdx.y;
    int fb = blockIdx.x * FS;
    int tid = threadIdx.x, w = tid >> 5, lane = tid & 31;
    int q  = lane >> 3;
    int li = lane & 7;

    const char* nbr_base = (const char*)&g_nbr32[(size_t)g * 512 * PADN];

    if (tid < 512) {
        dinv_s[tid] = g_dinv[g * 512 + tid];
        pc_s[tid]   = g_pc[g * 512 + tid];
    }
    if (tid >= 512 && tid < 528) *(unsigned*)(ubuf0 + 512 * UROWB + (tid - 512) * 4) = 0u;
    else if (tid >= 544 && tid < 560) *(unsigned*)(ubuf1 + 512 * UROWB + (tid - 544) * 4) = 0u;
    __syncthreads();

    int roff[4];
    int cntm[4];
    unsigned long long ddm[4];
    unsigned long long acc01[4], acc23[4];

    const char* xbase = (const char*)(xin + (size_t)g * 512 * FF + fb) + li * 16;
#pragma unroll
    for (int m = 0; m < 4; m++) {
        int pos = m * 128 + ((m & 1) ? (124 - 4 * w) : (4 * w)) + q;  // serpentine
        unsigned pc = pc_s[pos];
        int row = pc & 0xffffu;
        cntm[m] = pc >> 16;
        roff[m] = row << 6;
        float d = dinv_s[row];
        ddm[m] = packx2(d, d);
        float4 xv = *(const float4*)(xbase + (size_t)roff[m] * 8);
        acc01[m] = packx2(xv.x, xv.y);
        acc23[m] = packx2(xv.z, xv.w);
        uint2 uw;
        uw.x = packbf_from_x2(mulx2(ddm[m], acc01[m]));
        uw.y = packbf_from_x2(mulx2(ddm[m], acc23[m]));
        *(uint2*)(ubuf0 + roff[m] + li * 8) = uw;
    }
    __syncthreads();

    unsigned char* ucur = ubuf0;
    unsigned char* unew = ubuf1;
#pragma unroll 1
    for (int hop = 0; hop < 3; hop++) {
        const char* ucb = (const char*)ucur + li * 8;
#pragma unroll
        for (int m = 0; m < 4; m++) {
            const uint4* rowp = (const uint4*)(nbr_base + ((size_t)roff[m] << 2));
            int cnt4 = cntm[m];
            unsigned long long s01 = 0ull, s23 = 0ull;
            uint4 pk = __ldg(rowp);
#pragma unroll 1
            for (int e = 0; e < cnt4; e += 4) {
                uint4 nx = __ldg(rowp + (e >> 2) + 1);
                uint2 v0 = *(const uint2*)(ucb + pk.x);
                uint2 v1 = *(const uint2*)(ucb + pk.y);
                uint2 v2 = *(const uint2*)(ucb + pk.z);
                uint2 v3 = *(const uint2*)(ucb + pk.w);
                addx2(s01, bfpair(v0.x)); addx2(s23, bfpair(v0.y));
                addx2(s01, bfpair(v1.x)); addx2(s23, bfpair(v1.y));
                addx2(s01, bfpair(v2.x)); addx2(s23, bfpair(v2.y));
                addx2(s01, bfpair(v3.x)); addx2(s23, bfpair(v3.y));
                pk = nx;
            }
            unsigned long long z01 = mulx2(ddm[m], s01);
            unsigned long long z23 = mulx2(ddm[m], s23);
            addx2(acc01[m], z01); addx2(acc23[m], z23);
            if (hop < 2) {
                uint2 uw;
                uw.x = packbf_from_x2(mulx2(ddm[m], z01));
                uw.y = packbf_from_x2(mulx2(ddm[m], z23));
                *(uint2*)(unew + roff[m] + li * 8) = uw;
            }
        }
        __syncthreads();
        unsigned char* t = ucur; ucur = unew; unew = t;
    }

    char* ybase = (char*)(g_acc + (size_t)g * 512 * FF + fb) + li * 16;
#pragma unroll
    for (int m = 0; m < 4; m++) {
        float4 ov;
        unpackx2(acc01[m], ov.x, ov.y);
        unpackx2(acc23[m], ov.z, ov.w);
        *(float4*)(ybase + (size_t)roff[m] * 8) = ov;
    }
}

// ---------------- mma.sync GEMM + bias + relu ----------------
// 256 threads, warp tile 32x64 (2 m-tiles x 8 n-tiles). B (weights) fragments are
// loaded DIRECTLY FROM GLOBAL (64KB, L1-resident, shared by all CTAs) -> smem holds
// only A hi/lo (72KB) -> 2 CTAs/SM for load/compute overlap on the latency-bound
// A-load phase. MODE 0: write Y. MODE 1: fused relu column sums -> pool.
#define ASTR 136
#define GMM_AH 0
#define GMM_AL (GMM_AH + 128*ASTR*2)
#define GMM_BIAS (GMM_AL + 128*ASTR*2)
#define GMM_PART (GMM_BIAS + 128*4)
#define GEMM_MMA_SMEM (GMM_PART + 4*128*4)

__device__ __forceinline__ void mma16816(float* c, const unsigned* a, const unsigned* b) {
    asm volatile(
        "mma.sync.aligned.m16n8k16.row.col.f32.bf16.bf16.f32 "
        "{%0,%1,%2,%3}, {%4,%5,%6,%7}, {%8,%9}, {%0,%1,%2,%3};"
        : "+f"(c[0]), "+f"(c[1]), "+f"(c[2]), "+f"(c[3])
        : "r"(a[0]), "r"(a[1]), "r"(a[2]), "r"(a[3]), "r"(b[0]), "r"(b[1]));
}

template <int MODE>
__global__ void __launch_bounds__(256, 2) gemm_mma_kernel(
        const float* __restrict__ A, const unsigned int* __restrict__ wt,
        const float* __restrict__ bias, float* __restrict__ Y,
        float* __restrict__ pool) {
    extern __shared__ unsigned char smg[];
    unsigned short* Ah = (unsigned short*)(smg + GMM_AH);
    unsigned short* Al = (unsigned short*)(smg + GMM_AL);
    float* bias_s = (float*)(smg + GMM_BIAS);
    float* part   = (float*)(smg + GMM_PART);   // [4][128]

    int tid = threadIdx.x;
    int lane = tid & 31;
    int w = tid >> 5;
    int wr = w & 3;
    int wc = w >> 2;
    size_t rowbase = (size_t)blockIdx.x * 128;

    // A tiles: load fp32, split hi/lo into smem
    for (int idx = tid; idx < 8192; idx += 256) {
        int r = idx >> 6, p = idx & 63;
        float2 x = *(const float2*)(A + (rowbase + r) * 128 + 2 * p);
        __nv_bfloat16 h0 = __float2bfloat16(x.x);
        __nv_bfloat16 h1 = __float2bfloat16(x.y);
        __nv_bfloat16 l0 = __float2bfloat16(x.x - __bfloat162float(h0));
        __nv_bfloat16 l1 = __float2bfloat16(x.y - __bfloat162float(h1));
        *(unsigned int*)&Ah[r * ASTR + 2 * p] =
            (unsigned int)__bfloat16_as_ushort(h0) | ((unsigned int)__bfloat16_as_ushort(h1) << 16);
        *(unsigned int*)&Al[r * ASTR + 2 * p] =
            (unsigned int)__bfloat16_as_ushort(l0) | ((unsigned int)__bfloat16_as_ushort(l1) << 16);
    }
    if (tid < 128) bias_s[tid] = bias[tid];
    __syncthreads();

    float acc[2][8][4];
#pragma unroll
    for (int mt = 0; mt < 2; mt++)
#pragma unroll
        for (int nt = 0; nt < 8; nt++)
#pragma unroll
            for (int p = 0; p < 4; p++) acc[mt][nt][p] = 0.0f;

    int frow = lane >> 2;
    int fcolb = 2 * (lane & 3);
    int l3 = lane & 3;

#pragma unroll
    for (int kk = 0; kk < 8; kk++) {
        int kc = fcolb + 16 * kk;
        unsigned ah[2][4], al[2][4], bh[8][2], bl[8][2];
#pragma unroll
        for (int mt = 0; mt < 2; mt++) {
            int r0 = 32 * wr + 16 * mt + frow;
            ah[mt][0] = *(const unsigned*)&Ah[r0 * ASTR + kc];
            ah[mt][1] = *(const unsigned*)&Ah[(r0 + 8) * ASTR + kc];
            ah[mt][2] = *(const unsigned*)&Ah[r0 * ASTR + kc + 8];
            ah[mt][3] = *(const unsigned*)&Ah[(r0 + 8) * ASTR + kc + 8];
            al[mt][0] = *(const unsigned*)&Al[r0 * ASTR + kc];
            al[mt][1] = *(const unsigned*)&Al[(r0 + 8) * ASTR + kc];
            al[mt][2] = *(const unsigned*)&Al[r0 * ASTR + kc + 8];
            al[mt][3] = *(const unsigned*)&Al[(r0 + 8) * ASTR + kc + 8];
        }
        // B fragments straight from global (pair word idx = n*64 + 8*kk + l3 [+4])
#pragma unroll
        for (int nt = 0; nt < 8; nt++) {
            int n0 = 64 * wc + 8 * nt + frow;
            int base = n0 * 64 + 8 * kk + l3;
            bh[nt][0] = __ldg(&wt[base]);
            bh[nt][1] = __ldg(&wt[base + 4]);
            bl[nt][0] = __ldg(&wt[8192 + base]);
            bl[nt][1] = __ldg(&wt[8192 + base + 4]);
        }
#pragma unroll
        for (int mt = 0; mt < 2; mt++)
#pragma unroll
            for (int nt = 0; nt < 8; nt++) {
                mma16816(acc[mt][nt], ah[mt], bh[nt]);
                mma16816(acc[mt][nt], ah[mt], bl[nt]);
                mma16816(acc[mt][nt], al[mt], bh[nt]);
            }
    }

    if (MODE == 0) {
#pragma unroll
        for (int mt = 0; mt < 2; mt++) {
            size_t r0 = rowbase + 32 * wr + 16 * mt + frow;
#pragma unroll
            for (int nt = 0; nt < 8; nt++) {
                int col = 64 * wc + 8 * nt + fcolb;
                float b0 = bias_s[col], b1 = bias_s[col + 1];
                float2 v0, v1;
                float t;
                t = acc[mt][nt][0] + b0; v0.x = t > 0 ? t : 0;
                t = acc[mt][nt][1] + b1; v0.y = t > 0 ? t : 0;
                t = acc[mt][nt][2] + b0; v1.x = t > 0 ? t : 0;
                t = acc[mt][nt][3] + b1; v1.y = t > 0 ? t : 0;
                *(float2*)(Y + r0 * 128 + col)       = v0;
                *(float2*)(Y + (r0 + 8) * 128 + col) = v1;
            }
        }
    } else {
        float cs[8][2];
#pragma unroll
        for (int nt = 0; nt < 8; nt++) {
            int col = 64 * wc + 8 * nt + fcolb;
            float b0 = bias_s[col], b1 = bias_s[col + 1];
            float a0 = 0.f, a1 = 0.f;
#pragma unroll
            for (int mt = 0; mt < 2; mt++) {
                float t;
                t = acc[mt][nt][0] + b0; a0 += (t > 0 ? t : 0);
                t = acc[mt][nt][2] + b0; a0 += (t > 0 ? t : 0);
                t = acc[mt][nt][1] + b1; a1 += (t > 0 ? t : 0);
                t = acc[mt][nt][3] + b1; a1 += (t > 0 ? t : 0);
            }
            cs[nt][0] = a0; cs[nt][1] = a1;
        }
#pragma unroll
        for (int nt = 0; nt < 8; nt++) {
#pragma unroll
            for (int sft = 4; sft < 32; sft <<= 1) {
                cs[nt][0] += __shfl_xor_sync(0xffffffffu, cs[nt][0], sft);
                cs[nt][1] += __shfl_xor_sync(0xffffffffu, cs[nt][1], sft);
            }
        }
        if (lane < 4) {
#pragma unroll
            for (int nt = 0; nt < 8; nt++) {
                part[wr * 128 + 64 * wc + 8 * nt + 2 * lane]     = cs[nt][0];
                part[wr * 128 + 64 * wc + 8 * nt + 2 * lane + 1] = cs[nt][1];
            }
        }
        __syncthreads();
        if (tid < 128) {
            pool[(size_t)blockIdx.x * 128 + tid] =
                part[tid] + part[128 + tid] + part[256 + tid] + part[384 + tid];
        }
    }
}

// ---------------- head: mean pool (from partials) -> MLP ----------------
__global__ void __launch_bounds__(128) head_kernel(
        const float* __restrict__ pool,
        const float* __restrict__ Wr1, const float* __restrict__ br1,
        const float* __restrict__ Wr2, const float* __restrict__ br2,
        float* __restrict__ out) {
    __shared__ float hs[128];
    __shared__ float rs[64];
    int g = blockIdx.x;
    int tid = threadIdx.x;

    {
        const float* p = pool + (size_t)(4 * g) * 128 + tid;
        hs[tid] = (p[0] + p[128] + p[256] + p[384]) * (1.0f / 512.0f);
    }
    __syncthreads();

    if (tid < 64) {
        float a = br1[tid];
        for (int k = 0; k < 128; k++) a += hs[k] * Wr1[k * 64 + tid];
        rs[tid] = a > 0 ? a : 0;
    }
    __syncthreads();

    if (tid == 0) {
        float a = br2[0];
        for (int o = 0; o < 64; o++) a += rs[o] * Wr2[o];
        out[g] = a;
    }
}

// ---------------- launch ----------------
extern "C" void kernel_launch(void* const* d_in, const int* in_sizes, int n_in,
                              void* d_out, int out_size) {
    const float* X   = (const float*)d_in[0];
    const int*   ei  = (const int*)d_in[2];
    const float* W1  = (const float*)d_in[3];
    const float* b1  = (const float*)d_in[4];
    const float* W2  = (const float*)d_in[5];
    const float* b2  = (const float*)d_in[6];
    const float* Wr1 = (const float*)d_in[7];
    const float* br1 = (const float*)d_in[8];
    const float* Wr2 = (const float*)d_in[9];
    const float* br2 = (const float*)d_in[10];
    float* out = (float*)d_out;

    cudaFuncSetAttribute(poly_kernel, cudaFuncAttributeMaxDynamicSharedMemorySize, POLY_SMEM);
    cudaFuncSetAttribute(gemm_mma_kernel<0>, cudaFuncAttributeMaxDynamicSharedMemorySize, GEMM_MMA_SMEM);
    cudaFuncSetAttribute(gemm_mma_kernel<1>, cudaFuncAttributeMaxDynamicSharedMemorySize, GEMM_MMA_SMEM);

    void* yaddr = nullptr;  cudaGetSymbolAddress(&yaddr, g_y);
    float* Yp = (float*)yaddr;
    void* aaddr = nullptr;  cudaGetSymbolAddress(&aaddr, g_acc);
    const float* Ap = (const float*)aaddr;
    void* w1addr = nullptr; cudaGetSymbolAddress(&w1addr, g_wt1);
    void* w2addr = nullptr; cudaGetSymbolAddress(&w2addr, g_wt2);
    void* adjaddr = nullptr; cudaGetSymbolAddress(&adjaddr, g_adj);
    void* pooladdr = nullptr; cudaGetSymbolAddress(&pooladdr, g_pool);
    float* Pp = (float*)pooladdr;

    // adjacency (rebuilt every call; deterministic) — R14 launch sequence
    cudaMemsetAsync(adjaddr, 0, ADJ_WORDS * sizeof(unsigned int));
    build_adj_kernel<<<ETOT / 256, 256>>>(ei);
    expand_sort_kernel<<<BG, 512>>>();
    prep_w_kernel<<<64, 256>>>(W1, W2, (unsigned int*)w1addr, (unsigned int*)w2addr);

    dim3 pgrid(FF / FS, BG);

    // layer 1
    poly_kernel<<<pgrid, 1024, POLY_SMEM>>>(X);
    gemm_mma_kernel<0><<<NTOT / 128, 256, GEMM_MMA_SMEM>>>(Ap, (const unsigned int*)w1addr, b1, Yp, nullptr);
    // layer 2 (GEMM fuses the mean-pool partial sums; no Y write)
    poly_kernel<<<pgrid, 1024, POLY_SMEM>>>(Yp);
    gemm_mma_kernel<1><<<NTOT / 128, 256, GEMM_MMA_SMEM>>>(Ap, (const unsigned int*)w2addr, b2, nullptr, Pp);
    // head
    head_kernel<<<BG, 128>>>(Pp, Wr1, br1, Wr2, br2, out);
}